// round 16
// baseline (speedup 1.0000x reference)
#include <cuda_runtime.h>
#include <cuda_bf16.h>
#include <cstdint>

// Problem constants (fixed by the dataset problem)
#define T_TOK 8192
#define F_DIM 2048
#define E_NUM 16
#define R_DIM 16
#define O_DIM 2048
#define TOPK  4

// ---------------- scratch (static device globals; no allocations) -------------
__device__ float g_coeff[T_TOK * TOPK];   // softmax coeff * scaling, per (token, slot)
__device__ int   g_counts[E_NUM];         // tokens per expert
__device__ int   g_lists[E_NUM * T_TOK];  // entries: (token<<2)|slot
__device__ float g_zc0[T_TOK * 64];       // partial z (k-half 0), [ent][r]
__device__ float g_zc1[T_TOK * 64];       // partial z (k-half 1), [ent][r]
__device__ __nv_bfloat16 g_bs[(size_t)E_NUM * O_DIM * 48];  // [e][o][Bh|Bh|Bl]

// ---------------- mma.sync m16n8k16 bf16 (base sm_103 target, no 'a' needed) --
#define MMA16816(d, a, b)                                                      \
    asm volatile("mma.sync.aligned.m16n8k16.row.col.f32.bf16.bf16.f32 "        \
                 "{%0,%1,%2,%3}, {%4,%5,%6,%7}, {%8,%9}, {%0,%1,%2,%3};"       \
                 : "+f"((d)[0]), "+f"((d)[1]), "+f"((d)[2]), "+f"((d)[3])      \
                 : "r"((a)[0]), "r"((a)[1]), "r"((a)[2]), "r"((a)[3]),         \
                   "r"((b)[0]), "r"((b)[1]))

// ---------------- K1: B split prep + zero out + counter init ------------------
__global__ void __launch_bounds__(256) k_bcat(const float* __restrict__ Bst,
                                              float4* __restrict__ out4, int n4) {
    if (blockIdx.x == 0 && threadIdx.x < E_NUM) g_counts[threadIdx.x] = 0;
    int idx = blockIdx.x * 256 + threadIdx.x;        // 524288 = 16*2048*16
    int e = idx >> 15, rem = idx & 32767;
    int o = rem >> 4, r = rem & 15;
    float v = __ldg(&Bst[(size_t)e * O_DIM * R_DIM + o * R_DIM + r]);
    __nv_bfloat16 hi = __float2bfloat16(v);
    __nv_bfloat16 lo = __float2bfloat16(v - __bfloat162float(hi));
    size_t rb = (size_t)(e * O_DIM + o) * 48;
    g_bs[rb + r]      = hi;
    g_bs[rb + 16 + r] = hi;
    g_bs[rb + 32 + r] = lo;

    float4 z = make_float4(0.f, 0.f, 0.f, 0.f);
    for (int i = idx; i < n4; i += 2048 * 256) out4[i] = z;
}

// ---------------- K2: routing + dispatch (warp per token, proven) -------------
__global__ void __launch_bounds__(256) k_route(const float* __restrict__ x,
                                               const float* __restrict__ P,
                                               const float* __restrict__ scal_p) {
    int wg   = (blockIdx.x * 256 + threadIdx.x) >> 5;
    int lane = threadIdx.x & 31;

    const float4* x4 = (const float4*)(x + (size_t)wg * F_DIM);
    const float4* P4 = (const float4*)P;

    float acc[E_NUM];
#pragma unroll
    for (int e = 0; e < E_NUM; e++) acc[e] = 0.f;
#pragma unroll
    for (int it = 0; it < 16; it++) {
        float4 xv = __ldg(&x4[it * 32 + lane]);
#pragma unroll
        for (int e = 0; e < E_NUM; e++) {
            float4 pv = __ldg(&P4[e * 512 + it * 32 + lane]);
            acc[e] += xv.x * pv.x + xv.y * pv.y + xv.z * pv.z + xv.w * pv.w;
        }
    }
#pragma unroll
    for (int e = 0; e < E_NUM; e++) {
        float v = acc[e];
#pragma unroll
        for (int off = 16; off > 0; off >>= 1)
            v += __shfl_xor_sync(0xffffffffu, v, off);
        acc[e] = fabsf(v);   // arrow routing uses |cos|
    }

    int sel[TOPK];
    float sv[TOPK];
#pragma unroll
    for (int j = 0; j < TOPK; j++) {
        float best = -1.f;
        int bi = 0;
#pragma unroll
        for (int e = 0; e < E_NUM; e++)
            if (acc[e] > best) { best = acc[e]; bi = e; }
        sel[j] = bi; sv[j] = best;
#pragma unroll
        for (int e = 0; e < E_NUM; e++)
            if (e == bi) acc[e] = -2.f;   // sims >= 0; safe sentinel
    }
    float m = sv[0];
    float c[TOPK], s = 0.f;
#pragma unroll
    for (int j = 0; j < TOPK; j++) { c[j] = expf(sv[j] - m); s += c[j]; }
    float fold = __ldg(scal_p) / s;

    if (lane < TOPK) {
        int e = sel[lane];
        g_coeff[wg * TOPK + lane] = c[lane] * fold;
        int pos = atomicAdd(&g_counts[e], 1);
        g_lists[e * T_TOK + pos] = (wg << 2) | lane;
    }
}

// ---------------- K3: z-partials = x @ A_e^T (proven SIMT kernel) -------------
#define K2_TOK 256
__global__ void __launch_bounds__(256, 2) k_lora_A(const float* __restrict__ x,
                                                   const float* __restrict__ A) {
    int e    = blockIdx.x;
    int cnt  = g_counts[e];
    int base = blockIdx.y * K2_TOK;
    if (base >= cnt) return;
    int kh   = blockIdx.z;

    extern __shared__ float4 A_s4[];       // [16][256] float4
    const float4* Ae4 = (const float4*)(A + (size_t)e * R_DIM * F_DIM) + kh * 256;
    for (int i = threadIdx.x; i < R_DIM * 256; i += 256) {
        int r = i >> 8, c = i & 255;
        A_s4[i] = __ldg(&Ae4[r * 512 + c]);
    }
    __syncthreads();

    int w = threadIdx.x >> 5, lane = threadIdx.x & 31;
    int tt = lane >> 2, ks = lane & 3;

    int pos[4];
    const float4* xp[4];
#pragma unroll
    for (int i = 0; i < 4; i++) {
        pos[i] = base + w * 32 + tt + 8 * i;
        int ent = g_lists[e * T_TOK + min(pos[i], cnt - 1)];
        xp[i] = (const float4*)(x + (size_t)(ent >> 2) * F_DIM) + kh * 256;
    }

    float acc[4][R_DIM];
#pragma unroll
    for (int i = 0; i < 4; i++)
#pragma unroll
        for (int r = 0; r < R_DIM; r++) acc[i][r] = 0.f;

    float4 xv0 = __ldg(&xp[0][ks]);
    float4 xv1 = __ldg(&xp[1][ks]);
    float4 xv2 = __ldg(&xp[2][ks]);
    float4 xv3 = __ldg(&xp[3][ks]);

    for (int kk = 0; kk < 64; kk++) {
        float4 nx0, nx1, nx2, nx3;
        if (kk != 63) {
            int cn = kk * 4 + ks + 4;
            nx0 = __ldg(&xp[0][cn]); nx1 = __ldg(&xp[1][cn]);
            nx2 = __ldg(&xp[2][cn]); nx3 = __ldg(&xp[3][cn]);
        }
        int c = kk * 4 + ks;
#pragma unroll
        for (int r = 0; r < R_DIM; r++) {
            float4 av = A_s4[r * 256 + c];
            acc[0][r] += xv0.x * av.x + xv0.y * av.y + xv0.z * av.z + xv0.w * av.w;
            acc[1][r] += xv1.x * av.x + xv1.y * av.y + xv1.z * av.z + xv1.w * av.w;
            acc[2][r] += xv2.x * av.x + xv2.y * av.y + xv2.z * av.z + xv2.w * av.w;
            acc[3][r] += xv3.x * av.x + xv3.y * av.y + xv3.z * av.z + xv3.w * av.w;
        }
        xv0 = nx0; xv1 = nx1; xv2 = nx2; xv3 = nx3;
    }
#pragma unroll
    for (int i = 0; i < 4; i++)
#pragma unroll
        for (int r = 0; r < R_DIM; r++) {
            acc[i][r] += __shfl_xor_sync(0xffffffffu, acc[i][r], 1);
            acc[i][r] += __shfl_xor_sync(0xffffffffu, acc[i][r], 2);
        }

    float4* zdst = kh ? (float4*)g_zc1 : (float4*)g_zc0;
    int rb = ks * 4;
#pragma unroll
    for (int i = 0; i < 4; i++) {
        if (pos[i] < cnt) {
            int ent = g_lists[e * T_TOK + pos[i]];
            zdst[ent * 4 + ks] = make_float4(acc[i][rb], acc[i][rb + 1],
                                             acc[i][rb + 2], acc[i][rb + 3]);
        }
    }
}

// ---------------- K4: out += zc_split @ B_split^T via mma.sync bf16 ----------
// Grid (E, 64 entry-tiles of 128, 16 o-tiles of 128). 256 threads = 8 warps
// (warpM 0-3 x warpN 0-1; warp tile 32x64). K=48: [hi*Bh | lo*Bh | hi*Bl].
// Fragments via direct LDS per the documented m16n8k16 lane mapping (ZPAD=56
// keeps the 32 lane addresses on distinct banks). Epilogue stages the fp32
// tile in smem then does coalesced red.global.add.v4 (same pattern as R7).
#define ZPAD 56
#define OPAD 130
__global__ void __launch_bounds__(256) k_lora_B(float* __restrict__ out) {
    int e    = blockIdx.x;
    int cnt  = g_counts[e];
    int base = blockIdx.y * 128;
    if (base >= cnt) return;
    int n0   = blockIdx.z * 128;

    extern __shared__ char sm[];
    __nv_bfloat16* zc_s = (__nv_bfloat16*)sm;                 // [128][ZPAD]
    __nv_bfloat16* b_s  = (__nv_bfloat16*)(sm + 128 * ZPAD * 2);
    __shared__ int t_s[128];

    int tid = threadIdx.x;
    // ---- stage zc (bf16 hi/lo split, coeff folded) ----
    {
        int ei = tid >> 1, rh = (tid & 1) * 8;
        int pos = base + ei;
        if (pos < cnt) {
            int ent = g_lists[e * T_TOK + pos];
            if (rh == 0) t_s[ei] = ent >> 2;
            float cv = g_coeff[ent];
#pragma unroll
            for (int r = 0; r < 8; r++) {
                int rr = rh + r;
                float v = (g_zc0[ent * 16 + rr] + g_zc1[ent * 16 + rr]) * cv;
                __nv_bfloat16 hi = __float2bfloat16(v);
                __nv_bfloat16 lo = __float2bfloat16(v - __bfloat162float(hi));
                zc_s[ei * ZPAD + rr]      = hi;
                zc_s[ei * ZPAD + 16 + rr] = lo;
                zc_s[ei * ZPAD + 32 + rr] = hi;
            }
        } else {
            if (rh == 0) t_s[ei] = -1;
            __nv_bfloat16 z = __float2bfloat16(0.f);
#pragma unroll
            for (int r = 0; r < 8; r++) {
                int rr = rh + r;
                zc_s[ei * ZPAD + rr]      = z;
                zc_s[ei * ZPAD + 16 + rr] = z;
                zc_s[ei * ZPAD + 32 + rr] = z;
            }
        }
    }
    // ---- stage B slab: 128 o-rows x 48 bf16 ----
    {
        int o = tid >> 1, part = tid & 1;
        const uint4* src = (const uint4*)(g_bs + (size_t)(e * O_DIM + n0 + o) * 48);
#pragma unroll
        for (int u = 0; u < 3; u++) {
            uint4 v = __ldg(&src[part * 3 + u]);
            *(uint4*)&b_s[o * ZPAD + (part * 3 + u) * 8] = v;
        }
    }
    __syncthreads();

    int wid = tid >> 5, lane = tid & 31;
    int warpM = wid & 3, warpN = wid >> 2;
    int g = lane >> 2, t = lane & 3;
    int mrow0 = warpM * 32;
    int ncol0 = warpN * 64;

    float d[2][8][4];
#pragma unroll
    for (int mf = 0; mf < 2; mf++)
#pragma unroll
        for (int nf = 0; nf < 8; nf++)
#pragma unroll
            for (int q = 0; q < 4; q++) d[mf][nf][q] = 0.f;

#pragma unroll
    for (int kb = 0; kb < 3; kb++) {
        int kof = kb * 16 + 2 * t;
        uint32_t a[2][4], b[8][2];
#pragma unroll
        for (int mf = 0; mf < 2; mf++) {
            const __nv_bfloat16* ap = &zc_s[(mrow0 + mf * 16 + g) * ZPAD + kof];
            a[mf][0] = *(const uint32_t*)ap;
            a[mf][1] = *(const uint32_t*)(ap + 8 * ZPAD);
            a[mf][2] = *(const uint32_t*)(ap + 8);
            a[mf][3] = *(const uint32_t*)(ap + 8 * ZPAD + 8);
        }
#pragma unroll
        for (int nf = 0; nf < 8; nf++) {
            const __nv_bfloat16* bp = &b_s[(ncol0 + nf * 8 + g) * ZPAD + kof];
            b[nf][0] = *(const uint32_t*)bp;
            b[nf][1] = *(const uint32_t*)(bp + 8);
        }
#pragma unroll
        for (int mf = 0; mf < 2; mf++)
#pragma unroll
            for (int nf = 0; nf < 8; nf++)
                MMA16816(d[mf][nf], a[mf], b[nf]);
    }

    // ---- epilogue: stage fp32 tile to smem, then coalesced vector-red ----
    __syncthreads();                      // zc_s / b_s no longer needed
    float* out_s = (float*)sm;            // [128][OPAD]
#pragma unroll
    for (int mf = 0; mf < 2; mf++)
#pragma unroll
        for (int nf = 0; nf < 8; nf++) {
            int row = mrow0 + mf * 16 + g;
            int col = ncol0 + nf * 8 + 2 * t;
            *(float2*)&out_s[row * OPAD + col] =
                make_float2(d[mf][nf][0], d[mf][nf][1]);
            *(float2*)&out_s[(row + 8) * OPAD + col] =
                make_float2(d[mf][nf][2], d[mf][nf][3]);
        }
    __syncthreads();

#pragma unroll
    for (int it = 0; it < 16; it++) {
        int idx = it * 256 + tid;          // 0..4095
        int row = idx >> 5, c4 = idx & 31;
        int tok = t_s[row];
        if (tok >= 0) {
            const float* sp = &out_s[row * OPAD + c4 * 4];
            float* op = out + (size_t)tok * O_DIM + n0 + c4 * 4;
            asm volatile("red.global.add.v4.f32 [%0], {%1, %2, %3, %4};"
                         :: "l"(op), "f"(sp[0]), "f"(sp[1]), "f"(sp[2]), "f"(sp[3])
                         : "memory");
        }
    }
}

// ---------------- launcher ----------------------------------------------------
extern "C" void kernel_launch(void* const* d_in, const int* in_sizes, int n_in,
                              void* d_out, int out_size) {
    const float* x    = (const float*)d_in[0];  // (4,2048,2048)
    const float* P    = (const float*)d_in[1];  // (16,2048)
    const float* A    = (const float*)d_in[2];  // (16,16,2048)
    const float* Bst  = (const float*)d_in[3];  // (16,2048,16)
    const float* scal = (const float*)d_in[4];  // scalar
    float* out = (float*)d_out;

    const int SMEM_A = R_DIM * 256 * (int)sizeof(float4);   // 64 KB
    const int SMEM_B = 128 * OPAD * (int)sizeof(float);     // 66.6 KB (> stage 28.7 KB)
    cudaFuncSetAttribute(k_lora_A, cudaFuncAttributeMaxDynamicSharedMemorySize, SMEM_A);
    cudaFuncSetAttribute(k_lora_B, cudaFuncAttributeMaxDynamicSharedMemorySize, SMEM_B);

    int n4 = out_size / 4;
    // Launch order puts the new k_lora_B at profiled position 4.
    k_bcat<<<2048, 256>>>(Bst, (float4*)out, n4);            // B split + zero + counters
    k_route<<<T_TOK / 8, 256>>>(x, P, scal);
    k_lora_A<<<dim3(E_NUM, T_TOK / K2_TOK, 2), 256, SMEM_A>>>(x, A);
    k_lora_B<<<dim3(E_NUM, 64, 16), 256, SMEM_B>>>(out);
}

// round 17
// speedup vs baseline: 1.1009x; 1.1009x over previous
#include <cuda_runtime.h>
#include <cuda_bf16.h>
#include <cstdint>

// Problem constants (fixed by the dataset problem)
#define T_TOK 8192
#define F_DIM 2048
#define E_NUM 16
#define R_DIM 16
#define O_DIM 2048
#define TOPK  4

// ---------------- scratch (static device globals; no allocations) -------------
__device__ float g_coeff[T_TOK * TOPK];   // softmax coeff * scaling, per (token, slot)
__device__ int   g_counts[E_NUM];         // tokens per expert
__device__ int   g_lists[E_NUM * T_TOK];  // entries: (token<<2)|slot
__device__ float g_zc0[T_TOK * 64];       // partial z (k-half 0), [ent][r]
__device__ float g_zc1[T_TOK * 64];       // partial z (k-half 1), [ent][r]
__device__ __nv_bfloat16 g_bs[(size_t)E_NUM * O_DIM * 48];  // [e][o][Bh|Bh|Bl]

// ---------------- mma.sync m16n8k16 bf16 (base sm_103 target) -----------------
#define MMA16816(d, a, b)                                                      \
    asm volatile("mma.sync.aligned.m16n8k16.row.col.f32.bf16.bf16.f32 "        \
                 "{%0,%1,%2,%3}, {%4,%5,%6,%7}, {%8,%9}, {%0,%1,%2,%3};"       \
                 : "+f"((d)[0]), "+f"((d)[1]), "+f"((d)[2]), "+f"((d)[3])      \
                 : "r"((a)[0]), "r"((a)[1]), "r"((a)[2]), "r"((a)[3]),         \
                   "r"((b)[0]), "r"((b)[1]))

// ---------------- K1: B split prep + zero out + counter init ------------------
__global__ void __launch_bounds__(256) k_bcat(const float* __restrict__ Bst,
                                              float4* __restrict__ out4, int n4) {
    if (blockIdx.x == 0 && threadIdx.x < E_NUM) g_counts[threadIdx.x] = 0;
    int idx = blockIdx.x * 256 + threadIdx.x;        // 524288 = 16*2048*16
    int e = idx >> 15, rem = idx & 32767;
    int o = rem >> 4, r = rem & 15;
    float v = __ldg(&Bst[(size_t)e * O_DIM * R_DIM + o * R_DIM + r]);
    __nv_bfloat16 hi = __float2bfloat16(v);
    __nv_bfloat16 lo = __float2bfloat16(v - __bfloat162float(hi));
    size_t rb = (size_t)(e * O_DIM + o) * 48;
    g_bs[rb + r]      = hi;
    g_bs[rb + 16 + r] = hi;
    g_bs[rb + 32 + r] = lo;

    float4 z = make_float4(0.f, 0.f, 0.f, 0.f);
    for (int i = idx; i < n4; i += 2048 * 256) out4[i] = z;
}

// ---------------- K2: routing + dispatch (warp per token, proven) -------------
__global__ void __launch_bounds__(256) k_route(const float* __restrict__ x,
                                               const float* __restrict__ P,
                                               const float* __restrict__ scal_p) {
    int wg   = (blockIdx.x * 256 + threadIdx.x) >> 5;
    int lane = threadIdx.x & 31;

    const float4* x4 = (const float4*)(x + (size_t)wg * F_DIM);
    const float4* P4 = (const float4*)P;

    float acc[E_NUM];
#pragma unroll
    for (int e = 0; e < E_NUM; e++) acc[e] = 0.f;
#pragma unroll
    for (int it = 0; it < 16; it++) {
        float4 xv = __ldg(&x4[it * 32 + lane]);
#pragma unroll
        for (int e = 0; e < E_NUM; e++) {
            float4 pv = __ldg(&P4[e * 512 + it * 32 + lane]);
            acc[e] += xv.x * pv.x + xv.y * pv.y + xv.z * pv.z + xv.w * pv.w;
        }
    }
#pragma unroll
    for (int e = 0; e < E_NUM; e++) {
        float v = acc[e];
#pragma unroll
        for (int off = 16; off > 0; off >>= 1)
            v += __shfl_xor_sync(0xffffffffu, v, off);
        acc[e] = fabsf(v);   // arrow routing uses |cos|
    }

    int sel[TOPK];
    float sv[TOPK];
#pragma unroll
    for (int j = 0; j < TOPK; j++) {
        float best = -1.f;
        int bi = 0;
#pragma unroll
        for (int e = 0; e < E_NUM; e++)
            if (acc[e] > best) { best = acc[e]; bi = e; }
        sel[j] = bi; sv[j] = best;
#pragma unroll
        for (int e = 0; e < E_NUM; e++)
            if (e == bi) acc[e] = -2.f;   // sims >= 0; safe sentinel
    }
    float m = sv[0];
    float c[TOPK], s = 0.f;
#pragma unroll
    for (int j = 0; j < TOPK; j++) { c[j] = expf(sv[j] - m); s += c[j]; }
    float fold = __ldg(scal_p) / s;

    if (lane < TOPK) {
        int e = sel[lane];
        g_coeff[wg * TOPK + lane] = c[lane] * fold;
        int pos = atomicAdd(&g_counts[e], 1);
        g_lists[e * T_TOK + pos] = (wg << 2) | lane;
    }
}

// ---------------- K3: z-partials = x @ A_e^T (proven SIMT kernel) -------------
#define K2_TOK 256
__global__ void __launch_bounds__(256, 2) k_lora_A(const float* __restrict__ x,
                                                   const float* __restrict__ A) {
    int e    = blockIdx.x;
    int cnt  = g_counts[e];
    int base = blockIdx.y * K2_TOK;
    if (base >= cnt) return;
    int kh   = blockIdx.z;

    extern __shared__ float4 A_s4[];       // [16][256] float4
    const float4* Ae4 = (const float4*)(A + (size_t)e * R_DIM * F_DIM) + kh * 256;
    for (int i = threadIdx.x; i < R_DIM * 256; i += 256) {
        int r = i >> 8, c = i & 255;
        A_s4[i] = __ldg(&Ae4[r * 512 + c]);
    }
    __syncthreads();

    int w = threadIdx.x >> 5, lane = threadIdx.x & 31;
    int tt = lane >> 2, ks = lane & 3;

    int pos[4];
    const float4* xp[4];
#pragma unroll
    for (int i = 0; i < 4; i++) {
        pos[i] = base + w * 32 + tt + 8 * i;
        int ent = g_lists[e * T_TOK + min(pos[i], cnt - 1)];
        xp[i] = (const float4*)(x + (size_t)(ent >> 2) * F_DIM) + kh * 256;
    }

    float acc[4][R_DIM];
#pragma unroll
    for (int i = 0; i < 4; i++)
#pragma unroll
        for (int r = 0; r < R_DIM; r++) acc[i][r] = 0.f;

    float4 xv0 = __ldg(&xp[0][ks]);
    float4 xv1 = __ldg(&xp[1][ks]);
    float4 xv2 = __ldg(&xp[2][ks]);
    float4 xv3 = __ldg(&xp[3][ks]);

    for (int kk = 0; kk < 64; kk++) {
        float4 nx0, nx1, nx2, nx3;
        if (kk != 63) {
            int cn = kk * 4 + ks + 4;
            nx0 = __ldg(&xp[0][cn]); nx1 = __ldg(&xp[1][cn]);
            nx2 = __ldg(&xp[2][cn]); nx3 = __ldg(&xp[3][cn]);
        }
        int c = kk * 4 + ks;
#pragma unroll
        for (int r = 0; r < R_DIM; r++) {
            float4 av = A_s4[r * 256 + c];
            acc[0][r] += xv0.x * av.x + xv0.y * av.y + xv0.z * av.z + xv0.w * av.w;
            acc[1][r] += xv1.x * av.x + xv1.y * av.y + xv1.z * av.z + xv1.w * av.w;
            acc[2][r] += xv2.x * av.x + xv2.y * av.y + xv2.z * av.z + xv2.w * av.w;
            acc[3][r] += xv3.x * av.x + xv3.y * av.y + xv3.z * av.z + xv3.w * av.w;
        }
        xv0 = nx0; xv1 = nx1; xv2 = nx2; xv3 = nx3;
    }
#pragma unroll
    for (int i = 0; i < 4; i++)
#pragma unroll
        for (int r = 0; r < R_DIM; r++) {
            acc[i][r] += __shfl_xor_sync(0xffffffffu, acc[i][r], 1);
            acc[i][r] += __shfl_xor_sync(0xffffffffu, acc[i][r], 2);
        }

    float4* zdst = kh ? (float4*)g_zc1 : (float4*)g_zc0;
    int rb = ks * 4;
#pragma unroll
    for (int i = 0; i < 4; i++) {
        if (pos[i] < cnt) {
            int ent = g_lists[e * T_TOK + pos[i]];
            zdst[ent * 4 + ks] = make_float4(acc[i][rb], acc[i][rb + 1],
                                             acc[i][rb + 2], acc[i][rb + 3]);
        }
    }
}

// ---------------- K4: out += zc_split @ B_split^T via mma.sync, o-loop --------
// Grid (E, 64 entry-tiles). 256 threads = 8 warps (warpM 0-3 x warpN 0-1).
// zc (128 entries x 48) staged ONCE; loop over 16 o-chunks of 128, restaging
// only the 13 KB B slab. K=48: [hi*Bh | lo*Bh | hi*Bl]. Fragment mapping and
// red.v4 epilogue identical to the R16-verified version.
#define ZPAD 56
#define OPAD 132
#define SM_ZC 0
#define SM_B  (128 * ZPAD * 2)
#define SM_O  (SM_B + 128 * ZPAD * 2)
#define SM_TOT (SM_O + 128 * OPAD * 4)
__global__ void __launch_bounds__(256) k_lora_B(float* __restrict__ out) {
    int e    = blockIdx.x;
    int cnt  = g_counts[e];
    int base = blockIdx.y * 128;
    if (base >= cnt) return;

    extern __shared__ char sm[];
    __nv_bfloat16* zc_s  = (__nv_bfloat16*)(sm + SM_ZC);   // [128][ZPAD]
    __nv_bfloat16* b_s   = (__nv_bfloat16*)(sm + SM_B);    // [128][ZPAD]
    float*         out_s = (float*)(sm + SM_O);            // [128][OPAD]
    __shared__ int t_s[128];

    int tid = threadIdx.x;
    // ---- stage zc ONCE (bf16 hi/lo split, coeff folded) ----
    {
        int ei = tid >> 1, rh = (tid & 1) * 8;
        int pos = base + ei;
        if (pos < cnt) {
            int ent = g_lists[e * T_TOK + pos];
            if (rh == 0) t_s[ei] = ent >> 2;
            float cv = g_coeff[ent];
#pragma unroll
            for (int r = 0; r < 8; r++) {
                int rr = rh + r;
                float v = (g_zc0[ent * 16 + rr] + g_zc1[ent * 16 + rr]) * cv;
                __nv_bfloat16 hi = __float2bfloat16(v);
                __nv_bfloat16 lo = __float2bfloat16(v - __bfloat162float(hi));
                zc_s[ei * ZPAD + rr]      = hi;
                zc_s[ei * ZPAD + 16 + rr] = lo;
                zc_s[ei * ZPAD + 32 + rr] = hi;
            }
        } else {
            if (rh == 0) t_s[ei] = -1;
            __nv_bfloat16 z = __float2bfloat16(0.f);
#pragma unroll
            for (int r = 0; r < 8; r++) {
                int rr = rh + r;
                zc_s[ei * ZPAD + rr]      = z;
                zc_s[ei * ZPAD + 16 + rr] = z;
                zc_s[ei * ZPAD + 32 + rr] = z;
            }
        }
    }

    int wid = tid >> 5, lane = tid & 31;
    int warpM = wid & 3, warpN = wid >> 2;
    int g = lane >> 2, t = lane & 3;
    int mrow0 = warpM * 32;
    int ncol0 = warpN * 64;

    for (int og = 0; og < 16; og++) {
        int n0 = og * 128;
        __syncthreads();   // prev iter's b_s frag reads + out_s RED reads done
                           // (first iter: zc_s staging done)
        // ---- stage B chunk: 128 o-rows x 48 bf16 ----
        {
            int o = tid >> 1, part = tid & 1;
            const uint4* src = (const uint4*)(g_bs + (size_t)(e * O_DIM + n0 + o) * 48);
#pragma unroll
            for (int u = 0; u < 3; u++) {
                uint4 v = __ldg(&src[part * 3 + u]);
                *(uint4*)&b_s[o * ZPAD + (part * 3 + u) * 8] = v;
            }
        }
        __syncthreads();

        float d[2][8][4];
#pragma unroll
        for (int mf = 0; mf < 2; mf++)
#pragma unroll
            for (int nf = 0; nf < 8; nf++)
#pragma unroll
                for (int q = 0; q < 4; q++) d[mf][nf][q] = 0.f;

#pragma unroll
        for (int kb = 0; kb < 3; kb++) {
            int kof = kb * 16 + 2 * t;
            uint32_t a[2][4], b[8][2];
#pragma unroll
            for (int mf = 0; mf < 2; mf++) {
                const __nv_bfloat16* ap = &zc_s[(mrow0 + mf * 16 + g) * ZPAD + kof];
                a[mf][0] = *(const uint32_t*)ap;
                a[mf][1] = *(const uint32_t*)(ap + 8 * ZPAD);
                a[mf][2] = *(const uint32_t*)(ap + 8);
                a[mf][3] = *(const uint32_t*)(ap + 8 * ZPAD + 8);
            }
#pragma unroll
            for (int nf = 0; nf < 8; nf++) {
                const __nv_bfloat16* bp = &b_s[(ncol0 + nf * 8 + g) * ZPAD + kof];
                b[nf][0] = *(const uint32_t*)bp;
                b[nf][1] = *(const uint32_t*)(bp + 8);
            }
#pragma unroll
            for (int mf = 0; mf < 2; mf++)
#pragma unroll
                for (int nf = 0; nf < 8; nf++)
                    MMA16816(d[mf][nf], a[mf], b[nf]);
        }

        // ---- write d tile to out_s (per-warp disjoint regions) ----
#pragma unroll
        for (int mf = 0; mf < 2; mf++)
#pragma unroll
            for (int nf = 0; nf < 8; nf++) {
                int row = mrow0 + mf * 16 + g;
                int col = ncol0 + nf * 8 + 2 * t;
                *(float2*)&out_s[row * OPAD + col] =
                    make_float2(d[mf][nf][0], d[mf][nf][1]);
                *(float2*)&out_s[(row + 8) * OPAD + col] =
                    make_float2(d[mf][nf][2], d[mf][nf][3]);
            }
        __syncthreads();

        // ---- coalesced vector-red to gathered token rows ----
#pragma unroll
        for (int it = 0; it < 16; it++) {
            int idx = it * 256 + tid;          // 0..4095
            int row = idx >> 5, c4 = idx & 31;
            int tok = t_s[row];
            if (tok >= 0) {
                const float* sp = &out_s[row * OPAD + c4 * 4];
                float* op = out + (size_t)tok * O_DIM + n0 + c4 * 4;
                asm volatile("red.global.add.v4.f32 [%0], {%1, %2, %3, %4};"
                             :: "l"(op), "f"(sp[0]), "f"(sp[1]), "f"(sp[2]), "f"(sp[3])
                             : "memory");
            }
        }
    }
}

// ---------------- launcher ----------------------------------------------------
extern "C" void kernel_launch(void* const* d_in, const int* in_sizes, int n_in,
                              void* d_out, int out_size) {
    const float* x    = (const float*)d_in[0];  // (4,2048,2048)
    const float* P    = (const float*)d_in[1];  // (16,2048)
    const float* A    = (const float*)d_in[2];  // (16,16,2048)
    const float* Bst  = (const float*)d_in[3];  // (16,2048,16)
    const float* scal = (const float*)d_in[4];  // scalar
    float* out = (float*)d_out;

    const int SMEM_A = R_DIM * 256 * (int)sizeof(float4);   // 64 KB
    cudaFuncSetAttribute(k_lora_A, cudaFuncAttributeMaxDynamicSharedMemorySize, SMEM_A);
    cudaFuncSetAttribute(k_lora_B, cudaFuncAttributeMaxDynamicSharedMemorySize, SM_TOT);

    int n4 = out_size / 4;
    // Launch order puts k_lora_B at profiled position 4.
    k_bcat<<<2048, 256>>>(Bst, (float4*)out, n4);            // B split + zero + counters
    k_route<<<T_TOK / 8, 256>>>(x, P, scal);
    k_lora_A<<<dim3(E_NUM, T_TOK / K2_TOK, 2), 256, SMEM_A>>>(x, A);
    k_lora_B<<<dim3(E_NUM, 64), 256, SM_TOT>>>(out);
}